// round 3
// baseline (speedup 1.0000x reference)
#include <cuda_runtime.h>
#include <math.h>

#define H1 128
#define H2 256
#define NCLS 16
#define MAXN 65536

// ---- scratch (device globals: allocation-free per harness rules) ----
__device__ float g_y[MAXN * H1];       // relu(x @ Wp^T + bp)
__device__ float g_pooled[MAXN * H1];  // segment-max result
__device__ float g_h[MAXN * H1];       // combined hidden
__device__ float g_h2[MAXN * H2];      // MLP hidden

enum { ACT_RELU = 1, ACT_LEAKY = 2 };

// C[M,N] = act( A[M,K] @ B[N,K]^T (+ A2 @ B2^T) + bias[N] )
// BM=BN=64, BK=32, TM=TN=4, 256 threads. M%64==0, N%64==0, K%32==0 assumed.
template <int ACT, bool DUAL>
__global__ void __launch_bounds__(256) gemm_nt(
    const float* __restrict__ A, const float* __restrict__ B,
    const float* __restrict__ A2, const float* __restrict__ B2,
    const float* __restrict__ bias, float* __restrict__ C,
    int M, int N, int K)
{
    const int BM = 64, BN = 64, BK = 32, TM = 4, TN = 4;
    __shared__ float As[BM][BK + 1];
    __shared__ float Bs[BN][BK + 1];

    const int tid = threadIdx.x;
    const int tx = tid & 15;          // 16 col-threads
    const int ty = tid >> 4;          // 16 row-threads
    const int m0 = blockIdx.y * BM;
    const int n0 = blockIdx.x * BN;

    float acc[TM][TN];
    #pragma unroll
    for (int i = 0; i < TM; i++)
        #pragma unroll
        for (int j = 0; j < TN; j++) acc[i][j] = 0.0f;

    const int lr = tid >> 3;          // 0..31 (row within half-tile)
    const int lc = tid & 7;           // 0..7  (float4 column)

    const int nPass = DUAL ? 2 : 1;
    for (int pass = 0; pass < nPass; ++pass) {
        const float* Ap = (DUAL && pass) ? A2 : A;
        const float* Bp = (DUAL && pass) ? B2 : B;
        for (int k0 = 0; k0 < K; k0 += BK) {
            // load 64x32 A tile and 64x32 B tile (float4 global loads)
            #pragma unroll
            for (int rr = 0; rr < 2; rr++) {
                int r = lr + rr * 32;
                float4 va = *reinterpret_cast<const float4*>(
                    Ap + (size_t)(m0 + r) * K + k0 + lc * 4);
                As[r][lc * 4 + 0] = va.x; As[r][lc * 4 + 1] = va.y;
                As[r][lc * 4 + 2] = va.z; As[r][lc * 4 + 3] = va.w;
                float4 vb = *reinterpret_cast<const float4*>(
                    Bp + (size_t)(n0 + r) * K + k0 + lc * 4);
                Bs[r][lc * 4 + 0] = vb.x; Bs[r][lc * 4 + 1] = vb.y;
                Bs[r][lc * 4 + 2] = vb.z; Bs[r][lc * 4 + 3] = vb.w;
            }
            __syncthreads();
            #pragma unroll
            for (int k = 0; k < BK; k++) {
                float a[TM], b[TN];
                #pragma unroll
                for (int i = 0; i < TM; i++) a[i] = As[ty * TM + i][k];
                #pragma unroll
                for (int j = 0; j < TN; j++) b[j] = Bs[tx * TN + j][k];
                #pragma unroll
                for (int i = 0; i < TM; i++)
                    #pragma unroll
                    for (int j = 0; j < TN; j++) acc[i][j] += a[i] * b[j];
            }
            __syncthreads();
        }
    }

    // epilogue: bias + activation, float4 stores
    float4 bv = *reinterpret_cast<const float4*>(bias + n0 + tx * TN);
    const float bb[4] = {bv.x, bv.y, bv.z, bv.w};
    #pragma unroll
    for (int i = 0; i < TM; i++) {
        float4 o;
        float* op = &o.x;
        #pragma unroll
        for (int j = 0; j < TN; j++) {
            float v = acc[i][j] + bb[j];
            if (ACT == ACT_RELU)  v = fmaxf(v, 0.0f);
            if (ACT == ACT_LEAKY) v = (v > 0.0f) ? v : 0.01f * v;
            op[j] = v;
        }
        *reinterpret_cast<float4*>(
            C + (size_t)(m0 + ty * TM + i) * N + n0 + tx * TN) = o;
    }
}

// pooled init to 0 (matches segment_max -inf -> 0 replacement since y >= 0)
__global__ void zero_f4(float4* __restrict__ p, int n4)
{
    int i = blockIdx.x * blockDim.x + threadIdx.x;
    int stride = gridDim.x * blockDim.x;
    float4 z = make_float4(0.f, 0.f, 0.f, 0.f);
    for (; i < n4; i += stride) p[i] = z;
}

// one warp per edge: pooled[dst] = max(pooled[dst], y[src]) elementwise (128 floats)
// y >= 0 so int-bit atomicMax == float max.
__global__ void __launch_bounds__(256) scatter_max(
    const float* __restrict__ y, const int* __restrict__ src,
    const int* __restrict__ dst, int* __restrict__ pooled, int E)
{
    int w = (blockIdx.x * blockDim.x + threadIdx.x) >> 5;
    int lane = threadIdx.x & 31;
    if (w >= E) return;
    int s = src[w];
    int d = dst[w];
    float4 v = *reinterpret_cast<const float4*>(y + (size_t)s * H1 + lane * 4);
    int* p = pooled + (size_t)d * H1 + lane * 4;
    atomicMax(p + 0, __float_as_int(v.x));
    atomicMax(p + 1, __float_as_int(v.y));
    atomicMax(p + 2, __float_as_int(v.z));
    atomicMax(p + 3, __float_as_int(v.w));
}

// out[M,16] = sigmoid(h2[M,256] @ W2[16,256]^T + b2). 16 rows per block.
__global__ void __launch_bounds__(256) head_kernel(
    const float* __restrict__ h2, const float* __restrict__ W2,
    const float* __restrict__ b2, float* __restrict__ out, int M)
{
    __shared__ float ws[NCLS][H2 + 1];
    __shared__ float hs[16][H2 + 1];
    const int tid = threadIdx.x;
    const int m0 = blockIdx.x * 16;

    for (int i = tid; i < NCLS * H2; i += 256)
        ws[i / H2][i % H2] = W2[i];
    for (int i = tid; i < 16 * H2; i += 256)
        hs[i / H2][i % H2] = h2[(size_t)m0 * H2 + i];
    __syncthreads();

    const int r = tid >> 4;
    const int c = tid & 15;
    float acc = 0.0f;
    #pragma unroll 8
    for (int k = 0; k < H2; k++) acc += hs[r][k] * ws[c][k];
    acc += b2[c];
    out[(size_t)(m0 + r) * NCLS + c] = 1.0f / (1.0f + expf(-acc));
}

extern "C" void kernel_launch(void* const* d_in, const int* in_sizes, int n_in,
                              void* d_out, int out_size)
{
    const float* x  = (const float*)d_in[0];
    const float* Wp = (const float*)d_in[1];
    const float* bp = (const float*)d_in[2];
    const float* Ws = (const float*)d_in[3];
    const float* Wn = (const float*)d_in[4];
    const float* bn = (const float*)d_in[5];
    const float* W1 = (const float*)d_in[6];
    const float* b1 = (const float*)d_in[7];
    const float* W2 = (const float*)d_in[8];
    const float* b2 = (const float*)d_in[9];
    const int* src  = (const int*)d_in[10];
    const int* dst  = (const int*)d_in[11];
    float* out = (float*)d_out;

    const int M = in_sizes[0] / H1;   // IN_FEATS == H1 == 128
    const int E = in_sizes[10];

    float *y, *pooled, *h, *h2;
    cudaGetSymbolAddress((void**)&y, g_y);
    cudaGetSymbolAddress((void**)&pooled, g_pooled);
    cudaGetSymbolAddress((void**)&h, g_h);
    cudaGetSymbolAddress((void**)&h2, g_h2);

    // 1) pooled = 0
    zero_f4<<<2048, 256>>>((float4*)pooled, M * H1 / 4);

    // 2) y = relu(x @ Wp^T + bp)          [M,128]
    dim3 g1(H1 / 64, M / 64);
    gemm_nt<ACT_RELU, false><<<g1, 256>>>(x, Wp, nullptr, nullptr, bp, y,
                                          M, H1, H1);

    // 3) pooled[dst] = max over edges of y[src]
    int nblk = (E * 32 + 255) / 256;
    scatter_max<<<nblk, 256>>>(y, src, dst, (int*)pooled, E);

    // 4) h = leaky(x @ Ws^T + pooled @ Wn^T + bn)   [M,128]
    gemm_nt<ACT_LEAKY, true><<<g1, 256>>>(x, Ws, pooled, Wn, bn, h,
                                          M, H1, H1);

    // 5) h2 = leaky(h @ W1^T + b1)        [M,256]
    dim3 g2(H2 / 64, M / 64);
    gemm_nt<ACT_LEAKY, false><<<g2, 256>>>(h, W1, nullptr, nullptr, b1, h2,
                                           M, H2, H1);

    // 6) out = sigmoid(h2 @ W2^T + b2)    [M,16]
    head_kernel<<<M / 16, 256>>>(h2, W2, b2, out, M);
}

// round 5
// speedup vs baseline: 1.2186x; 1.2186x over previous
#include <cuda_runtime.h>
#include <math.h>

#define H1 128
#define H2 256
#define NCLS 16
#define MAXN 65536
#define MAXE 1048576

// ---- scratch (device globals: allocation-free per harness rules) ----
__device__ float g_y[MAXN * H1];        // relu(x @ Wp^T + bp)
__device__ float g_pooled[MAXN * H1];   // segment-max result
__device__ float g_h[MAXN * H1];        // combined hidden
__device__ float g_h2[MAXN * H2];       // MLP hidden
__device__ int   g_hist[MAXN];          // per-dst edge counts
__device__ int   g_offs[MAXN + 1];      // exclusive offsets
__device__ int   g_cursor[MAXN];        // scatter cursors
__device__ int   g_ssrc[MAXE];          // src ids bucketed by dst

enum { ACT_RELU = 1, ACT_LEAKY = 2 };

// ============================================================================
// SGEMM: C[M,N] = act( A[M,K] @ B[N,K]^T (+ A2 @ B2^T) + bias[N] )
// BM=BN=128, BK=16, 256 threads, 8x8 per thread (4+4 split row/col groups).
// Requires M%128==0, N%128==0, K%16==0.
// ============================================================================
template <int ACT, bool DUAL>
__global__ void __launch_bounds__(256, 2) gemm128(
    const float* __restrict__ A, const float* __restrict__ B,
    const float* __restrict__ A2, const float* __restrict__ B2,
    const float* __restrict__ bias, float* __restrict__ C,
    int M, int N, int K)
{
    const int BM = 128, BN = 128, BK = 16, PAD = 4;
    __shared__ float As[BK][BM + PAD];   // k-major
    __shared__ float Bs[BK][BN + PAD];

    const int tid = threadIdx.x;
    const int tx = tid & 15;             // col-thread (N)
    const int ty = tid >> 4;             // row-thread (M)
    const int m0 = blockIdx.y * BM;
    const int n0 = blockIdx.x * BN;

    // global-load mapping: 2 float4 per matrix per k-tile per thread
    const int lr = tid >> 2;             // 0..63
    const int lc = (tid & 3) * 4;        // 0,4,8,12

    float acc[8][8];
    #pragma unroll
    for (int i = 0; i < 8; i++)
        #pragma unroll
        for (int j = 0; j < 8; j++) acc[i][j] = 0.0f;

    const int nPass = DUAL ? 2 : 1;
    for (int pass = 0; pass < nPass; ++pass) {
        const float* Ap = (DUAL && pass) ? A2 : A;
        const float* Bp = (DUAL && pass) ? B2 : B;
        for (int k0 = 0; k0 < K; k0 += BK) {
            #pragma unroll
            for (int rr = 0; rr < 2; rr++) {
                int r = lr + rr * 64;
                float4 va = *reinterpret_cast<const float4*>(
                    Ap + (size_t)(m0 + r) * K + k0 + lc);
                As[lc + 0][r] = va.x; As[lc + 1][r] = va.y;
                As[lc + 2][r] = va.z; As[lc + 3][r] = va.w;
                float4 vb = *reinterpret_cast<const float4*>(
                    Bp + (size_t)(n0 + r) * K + k0 + lc);
                Bs[lc + 0][r] = vb.x; Bs[lc + 1][r] = vb.y;
                Bs[lc + 2][r] = vb.z; Bs[lc + 3][r] = vb.w;
            }
            __syncthreads();
            #pragma unroll
            for (int k = 0; k < BK; k++) {
                float a[8], b[8];
                *reinterpret_cast<float4*>(a)     =
                    *reinterpret_cast<const float4*>(&As[k][ty * 4]);
                *reinterpret_cast<float4*>(a + 4) =
                    *reinterpret_cast<const float4*>(&As[k][64 + ty * 4]);
                *reinterpret_cast<float4*>(b)     =
                    *reinterpret_cast<const float4*>(&Bs[k][tx * 4]);
                *reinterpret_cast<float4*>(b + 4) =
                    *reinterpret_cast<const float4*>(&Bs[k][64 + tx * 4]);
                #pragma unroll
                for (int i = 0; i < 8; i++)
                    #pragma unroll
                    for (int j = 0; j < 8; j++)
                        acc[i][j] += a[i] * b[j];
            }
            __syncthreads();
        }
    }

    // epilogue
    float bb[8];
    *reinterpret_cast<float4*>(bb) =
        *reinterpret_cast<const float4*>(bias + n0 + tx * 4);
    *reinterpret_cast<float4*>(bb + 4) =
        *reinterpret_cast<const float4*>(bias + n0 + 64 + tx * 4);
    #pragma unroll
    for (int ig = 0; ig < 2; ig++) {
        #pragma unroll
        for (int i = 0; i < 4; i++) {
            size_t row = (size_t)(m0 + ig * 64 + ty * 4 + i) * N;
            #pragma unroll
            for (int jg = 0; jg < 2; jg++) {
                float4 o;
                float* op = &o.x;
                #pragma unroll
                for (int j = 0; j < 4; j++) {
                    float v = acc[ig * 4 + i][jg * 4 + j] + bb[jg * 4 + j];
                    if (ACT == ACT_RELU)  v = fmaxf(v, 0.0f);
                    if (ACT == ACT_LEAKY) v = (v > 0.0f) ? v : 0.01f * v;
                    op[j] = v;
                }
                *reinterpret_cast<float4*>(C + row + n0 + jg * 64 + tx * 4) = o;
            }
        }
    }
}

// ============================================================================
// Edge bucketing (counting sort by dst) + segmented max
// ============================================================================
__global__ void zero_hist(int* __restrict__ hist, int n)
{
    int i = blockIdx.x * blockDim.x + threadIdx.x;
    if (i < n) hist[i] = 0;
}

__global__ void hist_kernel(const int* __restrict__ dst, int* __restrict__ hist, int E)
{
    int i = blockIdx.x * blockDim.x + threadIdx.x;
    if (i < E) atomicAdd(&hist[dst[i]], 1);
}

// one block, 1024 threads, 64 nodes each: exclusive scan of hist into offs/cursor
__global__ void __launch_bounds__(1024) scan_kernel(
    const int* __restrict__ hist, int* __restrict__ offs,
    int* __restrict__ cursor, int N)
{
    __shared__ int part[1024];
    const int tid = threadIdx.x;
    const int per = N / 1024;
    const int base = tid * per;
    int s = 0;
    for (int i = 0; i < per; i++) s += hist[base + i];
    part[tid] = s;
    __syncthreads();
    // Hillis-Steele inclusive scan
    for (int d = 1; d < 1024; d <<= 1) {
        int v = (tid >= d) ? part[tid - d] : 0;
        __syncthreads();
        part[tid] += v;
        __syncthreads();
    }
    int run = (tid == 0) ? 0 : part[tid - 1];
    for (int i = 0; i < per; i++) {
        offs[base + i] = run;
        cursor[base + i] = run;
        run += hist[base + i];
    }
    if (tid == 1023) offs[N] = run;
}

__global__ void scatter_edges(const int* __restrict__ src, const int* __restrict__ dst,
                              int* __restrict__ cursor, int* __restrict__ ssrc, int E)
{
    int i = blockIdx.x * blockDim.x + threadIdx.x;
    if (i < E) {
        int p = atomicAdd(&cursor[dst[i]], 1);
        ssrc[p] = src[i];
    }
}

// one warp per node: pooled[n] = max over bucketed edges of y[src] (0 if none)
__global__ void __launch_bounds__(256) pool_max(
    const float* __restrict__ y, const int* __restrict__ offs,
    const int* __restrict__ ssrc, float* __restrict__ pooled, int N)
{
    int w = (blockIdx.x * blockDim.x + threadIdx.x) >> 5;
    int lane = threadIdx.x & 31;
    if (w >= N) return;
    int e = offs[w], end = offs[w + 1];
    float4 m = make_float4(0.f, 0.f, 0.f, 0.f);
    for (; e + 1 < end; e += 2) {
        int s0 = ssrc[e], s1 = ssrc[e + 1];
        float4 v0 = *reinterpret_cast<const float4*>(y + (size_t)s0 * H1 + lane * 4);
        float4 v1 = *reinterpret_cast<const float4*>(y + (size_t)s1 * H1 + lane * 4);
        m.x = fmaxf(m.x, fmaxf(v0.x, v1.x));
        m.y = fmaxf(m.y, fmaxf(v0.y, v1.y));
        m.z = fmaxf(m.z, fmaxf(v0.z, v1.z));
        m.w = fmaxf(m.w, fmaxf(v0.w, v1.w));
    }
    if (e < end) {
        int s0 = ssrc[e];
        float4 v0 = *reinterpret_cast<const float4*>(y + (size_t)s0 * H1 + lane * 4);
        m.x = fmaxf(m.x, v0.x); m.y = fmaxf(m.y, v0.y);
        m.z = fmaxf(m.z, v0.z); m.w = fmaxf(m.w, v0.w);
    }
    *reinterpret_cast<float4*>(pooled + (size_t)w * H1 + lane * 4) = m;
}

// ============================================================================
// Head: out[M,16] = sigmoid(h2[M,256] @ W2[16,256]^T + b2), 16 rows/block
// ============================================================================
__global__ void __launch_bounds__(256) head_kernel(
    const float* __restrict__ h2, const float* __restrict__ W2,
    const float* __restrict__ b2, float* __restrict__ out, int M)
{
    __shared__ float ws[NCLS][H2 + 1];
    __shared__ float hs[16][H2 + 1];
    const int tid = threadIdx.x;
    const int m0 = blockIdx.x * 16;

    for (int i = tid; i < NCLS * H2; i += 256)
        ws[i / H2][i % H2] = W2[i];
    for (int i = tid; i < 16 * H2; i += 256)
        hs[i / H2][i % H2] = h2[(size_t)m0 * H2 + i];
    __syncthreads();

    const int r = tid >> 4;
    const int c = tid & 15;
    float acc = 0.0f;
    #pragma unroll 8
    for (int k = 0; k < H2; k++) acc += hs[r][k] * ws[c][k];
    acc += b2[c];
    out[(size_t)(m0 + r) * NCLS + c] = 1.0f / (1.0f + expf(-acc));
}

extern "C" void kernel_launch(void* const* d_in, const int* in_sizes, int n_in,
                              void* d_out, int out_size)
{
    const float* x  = (const float*)d_in[0];
    const float* Wp = (const float*)d_in[1];
    const float* bp = (const float*)d_in[2];
    const float* Ws = (const float*)d_in[3];
    const float* Wn = (const float*)d_in[4];
    const float* bn = (const float*)d_in[5];
    const float* W1 = (const float*)d_in[6];
    const float* b1 = (const float*)d_in[7];
    const float* W2 = (const float*)d_in[8];
    const float* b2 = (const float*)d_in[9];
    const int* src  = (const int*)d_in[10];
    const int* dst  = (const int*)d_in[11];
    float* out = (float*)d_out;

    const int M = in_sizes[0] / H1;   // IN_FEATS == H1 == 128
    const int E = in_sizes[10];

    float *y, *pooled, *h, *h2;
    int *hist, *offs, *cursor, *ssrc;
    cudaGetSymbolAddress((void**)&y, g_y);
    cudaGetSymbolAddress((void**)&pooled, g_pooled);
    cudaGetSymbolAddress((void**)&h, g_h);
    cudaGetSymbolAddress((void**)&h2, g_h2);
    cudaGetSymbolAddress((void**)&hist, g_hist);
    cudaGetSymbolAddress((void**)&offs, g_offs);
    cudaGetSymbolAddress((void**)&cursor, g_cursor);
    cudaGetSymbolAddress((void**)&ssrc, g_ssrc);

    // --- edge bucketing (independent of GEMMs; serialized stream) ---
    zero_hist<<<(M + 255) / 256, 256>>>(hist, M);
    hist_kernel<<<(E + 255) / 256, 256>>>(dst, hist, E);
    scan_kernel<<<1, 1024>>>(hist, offs, cursor, M);
    scatter_edges<<<(E + 255) / 256, 256>>>(src, dst, cursor, ssrc, E);

    // --- y = relu(x @ Wp^T + bp)  [M,128] ---
    dim3 g1(H1 / 128, M / 128);
    gemm128<ACT_RELU, false><<<g1, 256>>>(x, Wp, nullptr, nullptr, bp, y,
                                          M, H1, H1);

    // --- pooled[n] = segmented max of y over incoming edges ---
    pool_max<<<(M + 7) / 8, 256>>>(y, offs, ssrc, pooled, M);

    // --- h = leaky(x @ Ws^T + pooled @ Wn^T + bn)  [M,128] ---
    gemm128<ACT_LEAKY, true><<<g1, 256>>>(x, Ws, pooled, Wn, bn, h,
                                          M, H1, H1);

    // --- h2 = leaky(h @ W1^T + b1)  [M,256] ---
    dim3 g2(H2 / 128, M / 128);
    gemm128<ACT_LEAKY, false><<<g2, 256>>>(h, W1, nullptr, nullptr, b1, h2,
                                           M, H2, H1);

    // --- out = sigmoid(h2 @ W2^T + b2)  [M,16] ---
    head_kernel<<<M / 16, 256>>>(h2, W2, b2, out, M);
}